// round 6
// baseline (speedup 1.0000x reference)
#include <cuda_runtime.h>
#include <cuda_bf16.h>
#include <math.h>
#include <cstdint>

#define BB 2048
#define SS 23
#define DD 768
#define HH 8
#define HDD 96
#define LL 50
#define NT 184      // SS*HH (query,head) pairs
#define NTP 192     // padded
#define KA 6912     // 9*768
#define NL 64       // padded logits
#define NSPLIT 9

// ---------------- scratch ----------------
__device__ float g_qconst[SS*DD];
__device__ float g_sproj[NTP*DD];
__device__ __nv_bfloat16 g_sprojh[NTP*DD];
__device__ float g_c0[NTP];
__device__ float g_Mt[DD*NL];
__device__ float g_Wbig[KA*NL];
__device__ float g_bvM[NL];
__device__ float g_boutP[NL];
__device__ float g_msumP[NL];
__device__ float g_A[(size_t)BB*KA];
__device__ float g_P[(size_t)NSPLIT*BB*NL];

// ---------------- helpers ----------------
__device__ __forceinline__ uint32_t smem_u32(const void* p) {
    uint32_t a;
    asm("{ .reg .u64 t; cvta.to.shared.u64 t, %1; cvt.u32.u64 %0, t; }" : "=r"(a) : "l"(p));
    return a;
}
__device__ __forceinline__ void ldsm_x4(uint32_t& r0, uint32_t& r1, uint32_t& r2, uint32_t& r3,
                                        uint32_t addr) {
    asm volatile("ldmatrix.sync.aligned.m8n8.x4.shared.b16 {%0,%1,%2,%3}, [%4];"
                 : "=r"(r0), "=r"(r1), "=r"(r2), "=r"(r3) : "r"(addr));
}
__device__ __forceinline__ void ldsm_x2(uint32_t& r0, uint32_t& r1, uint32_t addr) {
    asm volatile("ldmatrix.sync.aligned.m8n8.x2.shared.b16 {%0,%1}, [%2];"
                 : "=r"(r0), "=r"(r1) : "r"(addr));
}
__device__ __forceinline__ void mma_bf16(float* d,
                                         uint32_t a0, uint32_t a1, uint32_t a2, uint32_t a3,
                                         uint32_t b0, uint32_t b1) {
    asm volatile(
        "mma.sync.aligned.m16n8k16.row.col.f32.bf16.bf16.f32 "
        "{%0,%1,%2,%3}, {%4,%5,%6,%7}, {%8,%9}, {%0,%1,%2,%3};"
        : "+f"(d[0]), "+f"(d[1]), "+f"(d[2]), "+f"(d[3])
        : "r"(a0), "r"(a1), "r"(a2), "r"(a3), "r"(b0), "r"(b1));
}
__device__ __forceinline__ uint32_t pack_bf16(float lo, float hi) {
    __nv_bfloat162 v = __floats2bfloat162_rn(lo, hi);
    return *reinterpret_cast<uint32_t*>(&v);
}

// ================= PA: p1_qconst (69 blocks) + p3_Mt (64 blocks, one l per block) ====
__global__ void __launch_bounds__(256) pA(const float* __restrict__ mt,
                                          const float* __restrict__ W,
                                          const float* __restrict__ bias,
                                          const float* __restrict__ pw,
                                          const float* __restrict__ ow) {
    int bx = blockIdx.x;
    if (bx < 69) {
        int idx = bx*256 + threadIdx.x;   // < 17664 exactly
        int sq = idx / DD, c = idx % DD;
        const float* m = mt + sq*DD;
        const float* w = W + (size_t)c*DD;
        float acc = bias[c];
        for (int k = 0; k < DD; k++) acc += m[k]*w[k];
        g_qconst[idx] = acc * rsqrtf((float)HDD);
    } else {
        int l = bx - 69;                  // 0..63
        int d = threadIdx.x;              // d, d+256, d+512
        float a0 = 0.f, a1 = 0.f, a2 = 0.f;
        if (l < LL) {
            const float* pr = pw + l*DD;
            for (int j = 0; j < DD; j++) {
                float p = pr[j];
                const float* orow = ow + (size_t)j*DD;
                a0 += p*orow[d]; a1 += p*orow[d+256]; a2 += p*orow[d+512];
            }
        }
        g_Mt[d*NL + l] = a0;
        g_Mt[(d+256)*NL + l] = a1;
        g_Mt[(d+512)*NL + l] = a2;
    }
}

// ================= PB: p2(576) + p4-tiled(192) + p4-tail(192) + p5a(1) + p5b(64) ====
#define PB_P2   576
#define PB_P4   (PB_P2 + 192)      // 768
#define PB_P4T  (PB_P4 + 192)      // 960
#define PB_P5A  (PB_P4T + 1)       // 961
#define PB_P5B  (PB_P5A + 64)      // 1025

__global__ void __launch_bounds__(256) pB(const float* __restrict__ W,
                                          const float* __restrict__ inb,
                                          const float* __restrict__ pw,
                                          const float* __restrict__ outb,
                                          const float* __restrict__ mt) {
    __shared__ float sh[96*64 + 96*32];
    int bx = blockIdx.x;
    int tid = threadIdx.x;

    if (bx < PB_P2) {
        int idx = bx*256 + tid;            // < 147456 exactly
        int t = idx / DD, d = idx % DD;
        if (t >= NT) { g_sproj[idx] = 0.f; g_sprojh[idx] = __float2bfloat16(0.f); return; }
        int sq = t / HH, h = t % HH;
        const float* q = g_qconst + sq*DD + h*HDD;
        float acc = 0.f;
        for (int j = 0; j < HDD; j++)
            acc += q[j] * W[(size_t)(DD + h*HDD + j)*DD + d];
        g_sproj[idx] = acc;
        g_sprojh[idx] = __float2bfloat16(acc);
    } else if (bx < PB_P4) {
        int b = bx - PB_P2;
        int h = b / 24, d0 = (b % 24) * 32;
        float* Mt_s = sh;
        float* W_s  = sh + 96*64;
        #pragma unroll
        for (int i = 0; i < 24; i++)
            Mt_s[i*256 + tid] = g_Mt[h*96*64 + i*256 + tid];
        #pragma unroll
        for (int i = 0; i < 12; i++) {
            int f = i*256 + tid;
            int t = f >> 5, j = f & 31;
            W_s[f] = W[(size_t)(2*DD + h*HDD + t)*DD + d0 + j];
        }
        __syncthreads();
        int d = tid & 31;
        int l0 = (tid >> 5) * 8;
        float acc[8];
        #pragma unroll
        for (int q = 0; q < 8; q++) acc[q] = 0.f;
        for (int t = 0; t < 96; t++) {
            float w = W_s[t*32 + d];
            float4 m0 = *(const float4*)(Mt_s + t*64 + l0);
            float4 m1 = *(const float4*)(Mt_s + t*64 + l0 + 4);
            acc[0] += m0.x*w; acc[1] += m0.y*w; acc[2] += m0.z*w; acc[3] += m0.w*w;
            acc[4] += m1.x*w; acc[5] += m1.y*w; acc[6] += m1.z*w; acc[7] += m1.w*w;
        }
        float* dst = g_Wbig + (size_t)(h*DD + d0 + d)*NL + l0;
        *(float4*)dst = make_float4(acc[0], acc[1], acc[2], acc[3]);
        *(float4*)(dst+4) = make_float4(acc[4], acc[5], acc[6], acc[7]);
    } else if (bx < PB_P4T) {
        int idx = (bx - PB_P4)*256 + tid;
        int l = idx & 63;
        int kk = idx >> 6;
        float v = (l < LL) ? pw[l*DD + kk] : 0.f;
        g_Wbig[(size_t)(HH*DD + kk)*NL + l] = v;
    } else if (bx < PB_P5A) {
        if (tid >= NTP) return;
        float acc = 0.f;
        if (tid < NT) {
            int sq = tid / HH, h = tid % HH;
            for (int j = 0; j < HDD; j++)
                acc += g_qconst[sq*DD + h*HDD + j] * inb[DD + h*HDD + j];
        }
        g_c0[tid] = acc;
    } else {
        int l = bx - PB_P5A;
        float a = 0.f, b2 = 0.f, c = 0.f;
        if (l < LL) {
            for (int d = tid; d < DD; d += 256) {
                float m = g_Mt[d*NL + l];
                float p = pw[l*DD + d];
                float ms = 0.f;
                #pragma unroll
                for (int s = 0; s < SS; s++) ms += mt[s*DD + d];
                a += m * inb[2*DD + d];
                b2 += p * outb[d];
                c += p * ms;
            }
        }
        #pragma unroll
        for (int o = 16; o > 0; o >>= 1) {
            a += __shfl_down_sync(0xFFFFFFFF, a, o);
            b2 += __shfl_down_sync(0xFFFFFFFF, b2, o);
            c += __shfl_down_sync(0xFFFFFFFF, c, o);
        }
        float* red = sh;
        int w = tid >> 5, ln = tid & 31;
        if (ln == 0) { red[w] = a; red[8+w] = b2; red[16+w] = c; }
        __syncthreads();
        if (tid == 0) {
            float sa = 0.f, sb = 0.f, sc2 = 0.f;
            for (int i = 0; i < 8; i++) { sa += red[i]; sb += red[8+i]; sc2 += red[16+i]; }
            g_bvM[l] = sa; g_boutP[l] = sb; g_msumP[l] = sc2;
        }
    }
}

// ================= F: fused scores MMA + softmax + u/csum (2 batches per CTA) ========
// smem layout (bytes):
#define F_CLS  0                       // bf16 [48][776]   = 74496
#define F_R2   74496                   // union: B dbuf (2*15360) / scores [48][200] f32 (38400)
#define F_MX   (F_R2 + 38400)          // 112896: [2][192] f32
#define F_DEN  (F_MX + 1536)           // 114432
#define F_WSM  (F_DEN + 1536)          // 115968: [2][192] f32 (h*23+sk)
#define F_C0S  (F_WSM + 1536)          // 117504: 192 f32
#define F_E    (F_C0S + 768)           // 118272: 48 int
#define F_NEX  (F_E + 192)             // 118464
#define F_SMEM 118528

__global__ void __launch_bounds__(256, 1) f_attn(const float* __restrict__ cls,
                                                 const int* __restrict__ mask) {
    extern __shared__ char smem[];
    uint32_t sb = smem_u32(smem);
    float* scS  = (float*)(smem + F_R2);
    float* mxS  = (float*)(smem + F_MX);
    float* denS = (float*)(smem + F_DEN);
    float* wsmS = (float*)(smem + F_WSM);
    float* c0S  = (float*)(smem + F_C0S);
    int*   eS   = (int*)(smem + F_E);
    int*   nexS = (int*)(smem + F_NEX);

    int tid = threadIdx.x;
    int wid = tid >> 5, lane = tid & 31;
    int g = lane >> 2, t4 = lane & 3;
    int l16 = lane & 15, lhi = lane >> 4;
    int l8 = lane & 7, lm8 = (lane >> 3) & 1;
    int b0 = blockIdx.x * 2;
    int wn = wid * 24;

    if (tid < NTP) c0S[tid] = g_c0[tid];
    if (tid < 46) eS[tid] = mask[b0*SS + tid];
    else if (tid < 48) eS[tid] = 0;

    // B loader indices: 192 rows x 4 segs of 8 halfwords = 768 segs, 3 per thread
    int br[3], bq[3];
    #pragma unroll
    for (int i = 0; i < 3; i++) { int f = i*256 + tid; br[i] = f >> 2; bq[i] = f & 3; }

    // preload B chunk 0
    uint4 pre[3];
    #pragma unroll
    for (int i = 0; i < 3; i++)
        pre[i] = *(const uint4*)(g_sprojh + (size_t)br[i]*DD + bq[i]*8);

    // load cls -> bf16 smem [48][776]
    const float* clsbase = cls + (size_t)b0*SS*DD;
    for (int idx = tid; idx < 48*192; idx += 256) {
        int r = idx / 192, q = idx - r*192;
        float4 v = make_float4(0.f, 0.f, 0.f, 0.f);
        if (r < 46) v = *(const float4*)(clsbase + (size_t)r*DD + q*4);
        uint2 pk;
        pk.x = pack_bf16(v.x, v.y); pk.y = pack_bf16(v.z, v.w);
        *(uint2*)(smem + F_CLS + (size_t)r*1552 + q*8) = pk;
    }
    // store B chunk 0
    #pragma unroll
    for (int i = 0; i < 3; i++)
        *(uint4*)(smem + F_R2 + br[i]*80 + bq[i]*16) = pre[i];
    __syncthreads();

    if (tid < 2) {
        int n = 0;
        for (int s = 0; s < SS; s++) n += (eS[tid*SS + s] != 0);
        nexS[tid] = n;
    }

    float acc[3][3][4];
    #pragma unroll
    for (int i = 0; i < 3; i++)
        #pragma unroll
        for (int j = 0; j < 3; j++)
            #pragma unroll
            for (int q = 0; q < 4; q++) acc[i][j][q] = 0.f;

    for (int c = 0; c < 24; c++) {
        int cb = c & 1;
        bool more = (c < 23);
        uint4 nb[3];
        if (more) {
            const __nv_bfloat16* bp = g_sprojh + (c + 1)*32;
            #pragma unroll
            for (int i = 0; i < 3; i++)
                nb[i] = *(const uint4*)(bp + (size_t)br[i]*DD + bq[i]*8);
        }
        uint32_t aCol = sb + F_CLS + (uint32_t)c*64 + lhi*16;
        uint32_t bCk = sb + F_R2 + cb*15360 + lm8*16;
        #pragma unroll
        for (int ks = 0; ks < 2; ks++) {
            uint32_t af[3][4];
            #pragma unroll
            for (int mt = 0; mt < 3; mt++)
                ldsm_x4(af[mt][0], af[mt][1], af[mt][2], af[mt][3],
                        aCol + (uint32_t)(mt*16 + l16)*1552 + ks*32);
            uint32_t b01[4], b2[2];
            ldsm_x4(b01[0], b01[1], b01[2], b01[3],
                    bCk + (uint32_t)(wn + l8 + lhi*8)*80 + ks*32);
            ldsm_x2(b2[0], b2[1],
                    bCk + (uint32_t)(wn + 16 + l8)*80 + ks*32);
            #pragma unroll
            for (int mt = 0; mt < 3; mt++) {
                mma_bf16(acc[mt][0], af[mt][0], af[mt][1], af[mt][2], af[mt][3], b01[0], b01[1]);
                mma_bf16(acc[mt][1], af[mt][0], af[mt][1], af[mt][2], af[mt][3], b01[2], b01[3]);
                mma_bf16(acc[mt][2], af[mt][0], af[mt][1], af[mt][2], af[mt][3], b2[0], b2[1]);
            }
        }
        if (more) {
            int dst = (c + 1) & 1;
            char* bs = smem + F_R2 + dst*15360;
            #pragma unroll
            for (int i = 0; i < 3; i++)
                *(uint4*)(bs + br[i]*80 + bq[i]*16) = nb[i];
            __syncthreads();
        }
    }
    __syncthreads();   // all MMA reads of B buffers done before scores overwrite them

    // epilogue: scores -> smem (+c0)
    #pragma unroll
    for (int mt = 0; mt < 3; mt++) {
        int m = mt*16 + g;
        float* r0 = scS + m*200;
        float* r1 = r0 + 8*200;
        #pragma unroll
        for (int nt = 0; nt < 3; nt++) {
            int n = wn + nt*8 + 2*t4;
            float c00 = c0S[n], c01 = c0S[n+1];
            r0[n]   = acc[mt][nt][0] + c00;
            r0[n+1] = acc[mt][nt][1] + c01;
            r1[n]   = acc[mt][nt][2] + c00;
            r1[n+1] = acc[mt][nt][3] + c01;
        }
    }
    __syncthreads();

    // softmax: mx/den per (b,t)
    for (int it = tid; it < 2*NT; it += 256) {
        int b = it / NT, t = it - b*NT;
        int sq = t >> 3;
        float m = -INFINITY, d = 0.f;
        if (nexS[b] > 0 && eS[b*SS + sq] == 0) {
            const float* col = scS + (b*SS)*200 + t;
            for (int sk = 0; sk < SS; sk++)
                if (eS[b*SS + sk]) m = fmaxf(m, col[sk*200]);
            for (int sk = 0; sk < SS; sk++)
                if (eS[b*SS + sk]) d += __expf(col[sk*200] - m);
        }
        mxS[b*192 + t] = m; denS[b*192 + t] = d;
    }
    __syncthreads();

    // wsm per (b,h,sk)
    for (int it = tid; it < 2*NT; it += 256) {
        int b = it / NT, r = it - b*NT;
        int h = r / SS, sk = r - h*SS;
        float w = 0.f;
        if (nexS[b] > 0 && eS[b*SS + sk]) {
            const float* row = scS + (b*SS + sk)*200;
            for (int sq = 0; sq < SS; sq++) {
                if (eS[b*SS + sq] == 0) {
                    int t = sq*HH + h;
                    w += __expf(row[t] - mxS[b*192 + t]) / denS[b*192 + t];
                }
            }
        }
        wsmS[b*192 + h*SS + sk] = w;
    }
    __syncthreads();

    // u + csum (fp32 cls from gmem, batched loads for MLP)
    for (int d0 = tid; d0 < DD; d0 += 256) {
        #pragma unroll
        for (int b = 0; b < 2; b++) {
            const float* cp = cls + ((size_t)(b0 + b)*SS)*DD + d0;
            float cv[SS];
            #pragma unroll
            for (int sk = 0; sk < SS; sk++) cv[sk] = cp[(size_t)sk*DD];
            float u[HH];
            #pragma unroll
            for (int h = 0; h < HH; h++) u[h] = 0.f;
            float csum = 0.f;
            #pragma unroll
            for (int sk = 0; sk < SS; sk++) {
                if (eS[b*SS + sk]) {
                    float cvv = cv[sk];
                    csum += cvv;
                    #pragma unroll
                    for (int h = 0; h < HH; h++)
                        u[h] += wsmS[b*192 + h*SS + sk] * cvv;
                }
            }
            float* arow = g_A + (size_t)(b0 + b)*KA;
            #pragma unroll
            for (int h = 0; h < HH; h++) arow[h*DD + d0] = u[h];
            arow[HH*DD + d0] = csum;
        }
    }
}

// ---------------- K3a: split-K logits GEMM ----------------
__global__ void __launch_bounds__(256) k3_gemm() {
    __shared__ float As[2][8][132];
    __shared__ float Bs[2][8][68];
    int tid = threadIdx.x;
    int m0 = blockIdx.x * 128;
    int split = blockIdx.y;
    int k0 = split * 768;
    int ty = tid >> 4, tx = tid & 15;
    int arow = tid >> 1, acol = (tid & 1) * 4;
    int bk = tid >> 5, bn = (tid & 31) * 2;

    const float* aptr = g_A + (size_t)(m0 + arow)*KA + k0 + acol;
    const float* bptr = g_Wbig + (size_t)(k0 + bk)*NL + bn;

    {
        float4 av = *(const float4*)aptr;
        As[0][acol+0][arow] = av.x; As[0][acol+1][arow] = av.y;
        As[0][acol+2][arow] = av.z; As[0][acol+3][arow] = av.w;
        float2 bv = *(const float2*)bptr;
        Bs[0][bk][bn+0] = bv.x; Bs[0][bk][bn+1] = bv.y;
    }
    __syncthreads();

    float acc[8][4];
    #pragma unroll
    for (int i = 0; i < 8; i++)
        #pragma unroll
        for (int j = 0; j < 4; j++) acc[i][j] = 0.f;

    const int NK = 768 / 8;
    for (int kt = 0; kt < NK; kt++) {
        int cur = kt & 1, nxt = cur ^ 1;
        float4 av; float2 bv;
        bool more = (kt + 1 < NK);
        if (more) {
            av = *(const float4*)(aptr + (kt+1)*8);
            bv = *(const float2*)(bptr + (size_t)(kt+1)*8*NL);
        }
        #pragma unroll
        for (int kk = 0; kk < 8; kk++) {
            float4 a0 = *(const float4*)&As[cur][kk][ty*8];
            float4 a1 = *(const float4*)&As[cur][kk][ty*8 + 4];
            float4 b0 = *(const float4*)&Bs[cur][kk][tx*4];
            float a[8] = {a0.x,a0.y,a0.z,a0.w,a1.x,a1.y,a1.z,a1.w};
            float b[4] = {b0.x,b0.y,b0.z,b0.w};
            #pragma unroll
            for (int i = 0; i < 8; i++)
                #pragma unroll
                for (int j = 0; j < 4; j++) acc[i][j] += a[i]*b[j];
        }
        if (more) {
            As[nxt][acol+0][arow] = av.x; As[nxt][acol+1][arow] = av.y;
            As[nxt][acol+2][arow] = av.z; As[nxt][acol+3][arow] = av.w;
            Bs[nxt][bk][bn+0] = bv.x; Bs[nxt][bk][bn+1] = bv.y;
            __syncthreads();
        }
    }

    #pragma unroll
    for (int i = 0; i < 8; i++) {
        int m = m0 + ty*8 + i;
        #pragma unroll
        for (int j = 0; j < 4; j++) {
            int n = tx*4 + j;
            g_P[((size_t)split*BB + m)*NL + n] = acc[i][j];
        }
    }
}

// ---------------- K3b: reduce splits + scalar terms ----------------
__global__ void k3b_final(const int* __restrict__ mask, const float* __restrict__ pb,
                          float* __restrict__ out) {
    int idx = blockIdx.x*256 + threadIdx.x;
    if (idx >= BB*NL) return;
    int b = idx / NL, l = idx % NL;
    if (l >= LL) return;
    int nex = 0;
    for (int s = 0; s < SS; s++) nex += (mask[b*SS + s] != 0);
    float r;
    if (nex > 0) {
        float acc = 0.f;
        for (int s = 0; s < NSPLIT; s++)
            acc += g_P[((size_t)s*BB + b)*NL + l];
        float nmiss = (float)(SS - nex);
        r = (acc + nmiss*(g_bvM[l] + g_boutP[l])) * (1.f/SS) + pb[l];
    } else {
        r = g_msumP[l] * (1.f/SS) + pb[l];
    }
    out[b*LL + l] = r;
}

// ---------------- launcher ----------------
extern "C" void kernel_launch(void* const* d_in, const int* in_sizes, int n_in,
                              void* d_out, int out_size) {
    const float* cls  = (const float*)d_in[0];
    const int*   mask = (const int*)  d_in[1];
    const float* mt   = (const float*)d_in[2];
    const float* ipw  = (const float*)d_in[3];
    const float* ipb  = (const float*)d_in[4];
    const float* opw  = (const float*)d_in[5];
    const float* opb  = (const float*)d_in[6];
    const float* pw   = (const float*)d_in[7];
    const float* pb   = (const float*)d_in[8];
    float* out = (float*)d_out;

    cudaFuncSetAttribute(f_attn, cudaFuncAttributeMaxDynamicSharedMemorySize, F_SMEM);

    pA<<<133, 256>>>(mt, ipw, ipb, pw, opw);
    pB<<<PB_P5B, 256>>>(ipw, ipb, pw, opb, mt);

    f_attn<<<BB/2, 256, F_SMEM>>>(cls, mask);
    dim3 g3(16, NSPLIT);
    k3_gemm<<<g3, 256>>>();
    k3b_final<<<(BB*NL + 255)/256, 256>>>(mask, pb, out);
}

// round 7
// speedup vs baseline: 1.3586x; 1.3586x over previous
#include <cuda_runtime.h>
#include <cuda_bf16.h>
#include <math.h>
#include <cstdint>

#define BB 2048
#define SS 23
#define DD 768
#define HH 8
#define HDD 96
#define LL 50
#define NT 184
#define NTP 192
#define KA 6912
#define NL 64
#define NSPLIT 18

// ---------------- scratch ----------------
__device__ float g_qconst[SS*DD];
__device__ float g_sproj[NTP*DD];
__device__ __nv_bfloat16 g_sprojh[NTP*DD];
__device__ float g_c0[NTP];
__device__ float g_Mt[DD*NL];
__device__ float g_Wbig[KA*NL];
__device__ float g_bvM[NL];
__device__ float g_boutP[NL];
__device__ float g_msumP[NL];
__device__ float g_scores[(size_t)BB*SS*NTP];
__device__ float g_A[(size_t)BB*KA];
__device__ float g_P[(size_t)NSPLIT*BB*NL];
// compaction
__device__ int g_rowidx[BB*SS + 64];
__device__ int g_rowstart[BB];
__device__ int g_nex[BB];
__device__ int g_sqmiss[BB*24];
__device__ int g_mtotal;

// ---------------- helpers ----------------
__device__ __forceinline__ uint32_t smem_u32(const void* p) {
    uint32_t a;
    asm("{ .reg .u64 t; cvta.to.shared.u64 t, %1; cvt.u32.u64 %0, t; }" : "=r"(a) : "l"(p));
    return a;
}
__device__ __forceinline__ void ldsm_x4(uint32_t& r0, uint32_t& r1, uint32_t& r2, uint32_t& r3,
                                        uint32_t addr) {
    asm volatile("ldmatrix.sync.aligned.m8n8.x4.shared.b16 {%0,%1,%2,%3}, [%4];"
                 : "=r"(r0), "=r"(r1), "=r"(r2), "=r"(r3) : "r"(addr));
}
__device__ __forceinline__ void mma_bf16(float* d,
                                         uint32_t a0, uint32_t a1, uint32_t a2, uint32_t a3,
                                         uint32_t b0, uint32_t b1) {
    asm volatile(
        "mma.sync.aligned.m16n8k16.row.col.f32.bf16.bf16.f32 "
        "{%0,%1,%2,%3}, {%4,%5,%6,%7}, {%8,%9}, {%0,%1,%2,%3};"
        : "+f"(d[0]), "+f"(d[1]), "+f"(d[2]), "+f"(d[3])
        : "r"(a0), "r"(a1), "r"(a2), "r"(a3), "r"(b0), "r"(b1));
}
__device__ __forceinline__ uint32_t pack_bf16(float lo, float hi) {
    __nv_bfloat162 v = __floats2bfloat162_rn(lo, hi);
    return *reinterpret_cast<uint32_t*>(&v);
}

// ================= PA: p1_qconst (69 blocks) + p3_Mt (64 blocks) =================
__global__ void __launch_bounds__(256) pA(const float* __restrict__ mt,
                                          const float* __restrict__ W,
                                          const float* __restrict__ bias,
                                          const float* __restrict__ pw,
                                          const float* __restrict__ ow) {
    int bx = blockIdx.x;
    if (bx < 69) {
        int idx = bx*256 + threadIdx.x;
        int sq = idx / DD, c = idx % DD;
        const float* m = mt + sq*DD;
        const float* w = W + (size_t)c*DD;
        float acc = bias[c];
        for (int k = 0; k < DD; k++) acc += m[k]*w[k];
        g_qconst[idx] = acc * rsqrtf((float)HDD);
    } else {
        int l = bx - 69;
        int d = threadIdx.x;
        float a0 = 0.f, a1 = 0.f, a2 = 0.f;
        if (l < LL) {
            const float* pr = pw + l*DD;
            for (int j = 0; j < DD; j++) {
                float p = pr[j];
                const float* orow = ow + (size_t)j*DD;
                a0 += p*orow[d]; a1 += p*orow[d+256]; a2 += p*orow[d+512];
            }
        }
        g_Mt[d*NL + l] = a0;
        g_Mt[(d+256)*NL + l] = a1;
        g_Mt[(d+512)*NL + l] = a2;
    }
}

// ================= PB =================
#define PB_P2   576
#define PB_P4   (PB_P2 + 192)
#define PB_P4T  (PB_P4 + 192)
#define PB_P5A  (PB_P4T + 1)
#define PB_P5B  (PB_P5A + 64)

__global__ void __launch_bounds__(256) pB(const float* __restrict__ W,
                                          const float* __restrict__ inb,
                                          const float* __restrict__ pw,
                                          const float* __restrict__ outb,
                                          const float* __restrict__ mt) {
    __shared__ float sh[96*64 + 96*32];
    int bx = blockIdx.x;
    int tid = threadIdx.x;

    if (bx < PB_P2) {
        int idx = bx*256 + tid;
        int t = idx / DD, d = idx % DD;
        if (t >= NT) { g_sproj[idx] = 0.f; g_sprojh[idx] = __float2bfloat16(0.f); return; }
        int sq = t / HH, h = t % HH;
        const float* q = g_qconst + sq*DD + h*HDD;
        float acc = 0.f;
        for (int j = 0; j < HDD; j++)
            acc += q[j] * W[(size_t)(DD + h*HDD + j)*DD + d];
        g_sproj[idx] = acc;
        g_sprojh[idx] = __float2bfloat16(acc);
    } else if (bx < PB_P4) {
        int b = bx - PB_P2;
        int h = b / 24, d0 = (b % 24) * 32;
        float* Mt_s = sh;
        float* W_s  = sh + 96*64;
        #pragma unroll
        for (int i = 0; i < 24; i++)
            Mt_s[i*256 + tid] = g_Mt[h*96*64 + i*256 + tid];
        #pragma unroll
        for (int i = 0; i < 12; i++) {
            int f = i*256 + tid;
            int t = f >> 5, j = f & 31;
            W_s[f] = W[(size_t)(2*DD + h*HDD + t)*DD + d0 + j];
        }
        __syncthreads();
        int d = tid & 31;
        int l0 = (tid >> 5) * 8;
        float acc[8];
        #pragma unroll
        for (int q = 0; q < 8; q++) acc[q] = 0.f;
        for (int t = 0; t < 96; t++) {
            float w = W_s[t*32 + d];
            float4 m0 = *(const float4*)(Mt_s + t*64 + l0);
            float4 m1 = *(const float4*)(Mt_s + t*64 + l0 + 4);
            acc[0] += m0.x*w; acc[1] += m0.y*w; acc[2] += m0.z*w; acc[3] += m0.w*w;
            acc[4] += m1.x*w; acc[5] += m1.y*w; acc[6] += m1.z*w; acc[7] += m1.w*w;
        }
        float* dst = g_Wbig + (size_t)(h*DD + d0 + d)*NL + l0;
        *(float4*)dst = make_float4(acc[0], acc[1], acc[2], acc[3]);
        *(float4*)(dst+4) = make_float4(acc[4], acc[5], acc[6], acc[7]);
    } else if (bx < PB_P4T) {
        int idx = (bx - PB_P4)*256 + tid;
        int l = idx & 63;
        int kk = idx >> 6;
        float v = (l < LL) ? pw[l*DD + kk] : 0.f;
        g_Wbig[(size_t)(HH*DD + kk)*NL + l] = v;
    } else if (bx < PB_P5A) {
        if (tid >= NTP) return;
        float acc = 0.f;
        if (tid < NT) {
            int sq = tid / HH, h = tid % HH;
            for (int j = 0; j < HDD; j++)
                acc += g_qconst[sq*DD + h*HDD + j] * inb[DD + h*HDD + j];
        }
        g_c0[tid] = acc;
    } else {
        int l = bx - PB_P5A;
        float a = 0.f, b2 = 0.f, c = 0.f;
        if (l < LL) {
            for (int d = tid; d < DD; d += 256) {
                float m = g_Mt[d*NL + l];
                float p = pw[l*DD + d];
                float ms = 0.f;
                #pragma unroll
                for (int s = 0; s < SS; s++) ms += mt[s*DD + d];
                a += m * inb[2*DD + d];
                b2 += p * outb[d];
                c += p * ms;
            }
        }
        #pragma unroll
        for (int o = 16; o > 0; o >>= 1) {
            a += __shfl_down_sync(0xFFFFFFFF, a, o);
            b2 += __shfl_down_sync(0xFFFFFFFF, b2, o);
            c += __shfl_down_sync(0xFFFFFFFF, c, o);
        }
        float* red = sh;
        int w = tid >> 5, ln = tid & 31;
        if (ln == 0) { red[w] = a; red[8+w] = b2; red[16+w] = c; }
        __syncthreads();
        if (tid == 0) {
            float sa = 0.f, sb = 0.f, sc2 = 0.f;
            for (int i = 0; i < 8; i++) { sa += red[i]; sb += red[8+i]; sc2 += red[16+i]; }
            g_bvM[l] = sa; g_boutP[l] = sb; g_msumP[l] = sc2;
        }
    }
}

// ================= PC: mask scan + row compaction (1 block, 1024 threads) ==========
__global__ void __launch_bounds__(1024) pC(const int* __restrict__ mask) {
    __shared__ int wsums[32];
    int tid = threadIdx.x;
    int b0 = tid*2, b1 = tid*2 + 1;
    int c0 = 0, c1 = 0;
    for (int s = 0; s < SS; s++) {
        c0 += (mask[b0*SS + s] != 0);
        c1 += (mask[b1*SS + s] != 0);
    }
    int tot = c0 + c1;
    int lane = tid & 31, w = tid >> 5;
    int v = tot;
    #pragma unroll
    for (int o = 1; o < 32; o <<= 1) {
        int x = __shfl_up_sync(0xFFFFFFFF, v, o);
        if (lane >= o) v += x;
    }
    if (lane == 31) wsums[w] = v;
    __syncthreads();
    if (w == 0) {
        int x = wsums[lane];
        #pragma unroll
        for (int o = 1; o < 32; o <<= 1) {
            int y = __shfl_up_sync(0xFFFFFFFF, x, o);
            if (lane >= o) x += y;
        }
        wsums[lane] = x;
    }
    __syncthreads();
    int incl = v + (w > 0 ? wsums[w-1] : 0);
    int ex = incl - tot;
    int s0 = ex, s1 = ex + c0;
    g_rowstart[b0] = s0; g_rowstart[b1] = s1;
    g_nex[b0] = c0; g_nex[b1] = c1;
    int p = s0, jm = 0;
    for (int s = 0; s < SS; s++) {
        if (mask[b0*SS + s]) g_rowidx[p++] = b0*SS + s;
        else g_sqmiss[b0*24 + (jm++)] = s;
    }
    p = s1; jm = 0;
    for (int s = 0; s < SS; s++) {
        if (mask[b1*SS + s]) g_rowidx[p++] = b1*SS + s;
        else g_sqmiss[b1*24 + (jm++)] = s;
    }
    if (tid == 1023) {
        g_mtotal = incl;
        for (int i = 0; i < 64; i++) g_rowidx[incl + i] = 0;
    }
}

// ---------------- K1: compacted scores GEMM (existing rows only) ----------------
#define SKW 40
#define K1_ABUF 5120
#define K1_BBUF 15360
#define K1_BOFF (2*K1_ABUF)
#define K1_RIDX (K1_BOFF + 2*K1_BBUF)   // 40960
#define K1_SMEM (K1_RIDX + 256)         // 41216
#define K1_NCHUNK 24

__global__ void __launch_bounds__(256, 2) k1_mma(const float* __restrict__ cls) {
    extern __shared__ char smem[];
    uint32_t sb = smem_u32(smem);
    int* ridx = (int*)(smem + K1_RIDX);

    int tid = threadIdx.x;
    int wid = tid >> 5;
    int lane = tid & 31;
    int g = lane >> 2, t4 = lane & 3;
    int l16 = lane & 15, lhi = lane >> 4;
    int l8 = lane & 7, lm8 = (lane >> 3) & 1;

    int mtotal = g_mtotal;
    int m0 = blockIdx.x * 64;
    if (m0 >= mtotal) return;

    if (tid < 64) ridx[tid] = g_rowidx[m0 + tid];
    __syncthreads();

    int wm = (wid & 1) * 32;
    int wn = (wid >> 1) * 48;

    int arow = tid >> 2, aq = tid & 3;
    const float* agp = cls + (size_t)ridx[arow]*DD + aq*8;
    uint32_t asts = (uint32_t)(arow*SKW + aq*8)*2;
    int br[3], bq[3];
    #pragma unroll
    for (int i = 0; i < 3; i++) { int f = i*256 + tid; br[i] = f >> 2; bq[i] = f & 3; }
    const __nv_bfloat16* bgp[3];
    uint32_t bsts[3];
    #pragma unroll
    for (int i = 0; i < 3; i++) {
        bgp[i] = g_sprojh + (size_t)br[i]*DD + bq[i]*8;
        bsts[i] = (uint32_t)K1_BOFF + (uint32_t)(br[i]*SKW + bq[i]*8)*2;
    }

    uint32_t aAddr = sb + ((wm + l16)*SKW + lhi*8)*2;
    uint32_t bAddr = sb + K1_BOFF + ((wn + l8 + lhi*8)*SKW + lm8*8)*2;

    // preload chunk 0
    {
        float4 v0 = *(const float4*)agp;
        float4 v1 = *(const float4*)(agp + 4);
        uint4 pk;
        pk.x = pack_bf16(v0.x, v0.y); pk.y = pack_bf16(v0.z, v0.w);
        pk.z = pack_bf16(v1.x, v1.y); pk.w = pack_bf16(v1.z, v1.w);
        *(uint4*)(smem + asts) = pk;
        #pragma unroll
        for (int i = 0; i < 3; i++)
            *(uint4*)(smem + bsts[i]) = *(const uint4*)bgp[i];
    }
    __syncthreads();

    float acc[2][6][4];
    #pragma unroll
    for (int i = 0; i < 2; i++)
        #pragma unroll
        for (int j = 0; j < 6; j++)
            #pragma unroll
            for (int q = 0; q < 4; q++) acc[i][j][q] = 0.f;

    for (int c = 0; c < K1_NCHUNK; c++) {
        int cb = c & 1;
        bool more = (c + 1 < K1_NCHUNK);
        float4 v0, v1; uint4 wb[3];
        if (more) {
            int kc = (c + 1) * 32;
            v0 = *(const float4*)(agp + kc);
            v1 = *(const float4*)(agp + kc + 4);
            #pragma unroll
            for (int i = 0; i < 3; i++)
                wb[i] = *(const uint4*)(bgp[i] + kc);
        }

        uint32_t aB = aAddr + cb*K1_ABUF;
        uint32_t bB = bAddr + cb*K1_BBUF;
        #pragma unroll
        for (int ks = 0; ks < 2; ks++) {
            uint32_t af[2][4];
            ldsm_x4(af[0][0], af[0][1], af[0][2], af[0][3], aB + ks*32);
            ldsm_x4(af[1][0], af[1][1], af[1][2], af[1][3], aB + 16*SKW*2 + ks*32);
            uint32_t bf[6][2];
            #pragma unroll
            for (int np = 0; np < 3; np++)
                ldsm_x4(bf[2*np][0], bf[2*np][1], bf[2*np+1][0], bf[2*np+1][1],
                        bB + np*16*SKW*2 + ks*32);
            #pragma unroll
            for (int mt = 0; mt < 2; mt++)
                #pragma unroll
                for (int nt = 0; nt < 6; nt++)
                    mma_bf16(acc[mt][nt], af[mt][0], af[mt][1], af[mt][2], af[mt][3],
                             bf[nt][0], bf[nt][1]);
        }

        if (more) {
            int nb = (c + 1) & 1;
            uint4 pk;
            pk.x = pack_bf16(v0.x, v0.y); pk.y = pack_bf16(v0.z, v0.w);
            pk.z = pack_bf16(v1.x, v1.y); pk.w = pack_bf16(v1.z, v1.w);
            *(uint4*)(smem + asts + nb*K1_ABUF) = pk;
            #pragma unroll
            for (int i = 0; i < 3; i++)
                *(uint4*)(smem + bsts[i] + nb*K1_BBUF) = wb[i];
            __syncthreads();
        }
    }

    #pragma unroll
    for (int mt = 0; mt < 2; mt++) {
        int m = m0 + wm + mt*16 + g;
        float* row0 = g_scores + (size_t)m * NTP;
        float* row1 = row0 + 8*NTP;
        #pragma unroll
        for (int nt = 0; nt < 6; nt++) {
            int n = wn + nt*8 + 2*t4;
            float c00 = g_c0[n], c01 = g_c0[n+1];
            *(float2*)(row0 + n) = make_float2(acc[mt][nt][0] + c00, acc[mt][nt][1] + c01);
            *(float2*)(row1 + n) = make_float2(acc[mt][nt][2] + c00, acc[mt][nt][3] + c01);
        }
    }
}

// ---------------- K2: compacted softmax + u/csum ----------------
__global__ void __launch_bounds__(256) k2_attn(const float* __restrict__ cls,
                                               const int* __restrict__ mask) {
    __shared__ float sc[SS][200];
    __shared__ float mx[NTP], den[NTP];
    __shared__ float wsm[HH*SS];
    __shared__ int e[SS], sklist[SS], sqm[SS];
    int b = blockIdx.x;
    int tid = threadIdx.x;

    int nex = g_nex[b];
    int rs = g_rowstart[b];
    int nmiss = SS - nex;

    if (tid < SS) {
        e[tid] = mask[b*SS + tid];
        sqm[tid] = g_sqmiss[b*24 + tid];
    }
    if (tid < nex) sklist[tid] = g_rowidx[rs + tid] - b*SS;
    for (int idx = tid; idx < nex*NTP; idx += 256)
        sc[idx / NTP][idx % NTP] = g_scores[(size_t)(rs + idx / NTP)*NTP + (idx % NTP)];
    __syncthreads();

    if (tid < NT) {
        int sq = tid >> 3;
        float m = -INFINITY, d = 0.f;
        if (nex > 0 && e[sq] == 0) {
            for (int i = 0; i < nex; i++) m = fmaxf(m, sc[i][tid]);
            for (int i = 0; i < nex; i++) d += __expf(sc[i][tid] - m);
        }
        mx[tid] = m; den[tid] = d;
    }
    __syncthreads();

    if (tid < HH*SS) {
        int h = tid / SS, i = tid - (tid/SS)*SS;
        float w = 0.f;
        if (i < nex) {
            for (int j = 0; j < nmiss; j++) {
                int t = sqm[j]*HH + h;
                w += __expf(sc[i][t] - mx[t]) / den[t];
            }
        }
        wsm[h*SS + i] = w;
    }
    __syncthreads();

    // u + csum: 192 threads, float4 per thread
    if (tid < 192) {
        int d0 = tid * 4;
        float4 u[HH];
        #pragma unroll
        for (int h = 0; h < HH; h++) u[h] = make_float4(0.f,0.f,0.f,0.f);
        float4 csum = make_float4(0.f,0.f,0.f,0.f);
        for (int i = 0; i < nex; i++) {
            int sk = sklist[i];
            float4 c = *(const float4*)(cls + ((size_t)b*SS + sk)*DD + d0);
            csum.x += c.x; csum.y += c.y; csum.z += c.z; csum.w += c.w;
            #pragma unroll
            for (int h = 0; h < HH; h++) {
                float w = wsm[h*SS + i];
                u[h].x += w*c.x; u[h].y += w*c.y; u[h].z += w*c.z; u[h].w += w*c.w;
            }
        }
        float* arow = g_A + (size_t)b * KA;
        #pragma unroll
        for (int h = 0; h < HH; h++) *(float4*)(arow + h*DD + d0) = u[h];
        *(float4*)(arow + HH*DD + d0) = csum;
    }
}

// ---------------- K3a: split-K logits GEMM (M=64, 18 splits) ----------------
__global__ void __launch_bounds__(256) k3_gemm() {
    __shared__ float As[2][8][68];
    __shared__ float Bs[2][8][68];
    int tid = threadIdx.x;
    int m0 = blockIdx.x * 64;
    int split = blockIdx.y;
    int k0 = split * 384;
    int ty = tid >> 4, tx = tid & 15;
    int arow = tid >> 2, acol = (tid & 3) * 2;
    int bk = tid >> 5, bn = (tid & 31) * 2;

    const float* aptr = g_A + (size_t)(m0 + arow)*KA + k0 + acol;
    const float* bptr = g_Wbig + (size_t)(k0 + bk)*NL + bn;

    {
        float2 av = *(const float2*)aptr;
        As[0][acol][arow] = av.x; As[0][acol+1][arow] = av.y;
        float2 bv = *(const float2*)bptr;
        Bs[0][bk][bn] = bv.x; Bs[0][bk][bn+1] = bv.y;
    }
    __syncthreads();

    float acc[4][4];
    #pragma unroll
    for (int i = 0; i < 4; i++)
        #pragma unroll
        for (int j = 0; j < 4; j++) acc[i][j] = 0.f;

    const int NK = 48;
    for (int kt = 0; kt < NK; kt++) {
        int cur = kt & 1, nxt = cur ^ 1;
        float2 av, bv;
        bool more = (kt + 1 < NK);
        if (more) {
            av = *(const float2*)(aptr + (kt+1)*8);
            bv = *(const float2*)(bptr + (size_t)(kt+1)*8*NL);
        }
        #pragma unroll
        for (int kk = 0; kk < 8; kk++) {
            float4 a0 = *(const float4*)&As[cur][kk][ty*4];
            float4 b0 = *(const float4*)&Bs[cur][kk][tx*4];
            float a[4] = {a0.x,a0.y,a0.z,a0.w};
            float bb[4] = {b0.x,b0.y,b0.z,b0.w};
            #pragma unroll
            for (int i = 0; i < 4; i++)
                #pragma unroll
                for (int j = 0; j < 4; j++) acc[i][j] += a[i]*bb[j];
        }
        if (more) {
            As[nxt][acol][arow] = av.x; As[nxt][acol+1][arow] = av.y;
            Bs[nxt][bk][bn] = bv.x; Bs[nxt][bk][bn+1] = bv.y;
            __syncthreads();
        }
    }

    #pragma unroll
    for (int i = 0; i < 4; i++) {
        int m = m0 + ty*4 + i;
        #pragma unroll
        for (int j = 0; j < 4; j++) {
            int n = tx*4 + j;
            g_P[((size_t)split*BB + m)*NL + n] = acc[i][j];
        }
    }
}

// ---------------- K3b ----------------
__global__ void k3b_final(const int* __restrict__ mask, const float* __restrict__ pb,
                          float* __restrict__ out) {
    int idx = blockIdx.x*256 + threadIdx.x;
    if (idx >= BB*NL) return;
    int b = idx / NL, l = idx % NL;
    if (l >= LL) return;
    int nex = g_nex[b];
    float r;
    if (nex > 0) {
        float acc = 0.f;
        for (int s = 0; s < NSPLIT; s++)
            acc += g_P[((size_t)s*BB + b)*NL + l];
        float nmiss = (float)(SS - nex);
        r = (acc + nmiss*(g_bvM[l] + g_boutP[l])) * (1.f/SS) + pb[l];
    } else {
        r = g_msumP[l] * (1.f/SS) + pb[l];
    }
    out[b*LL + l] = r;
}

// ---------------- launcher ----------------
extern "C" void kernel_launch(void* const* d_in, const int* in_sizes, int n_in,
                              void* d_out, int out_size) {
    const float* cls  = (const float*)d_in[0];
    const int*   mask = (const int*)  d_in[1];
    const float* mt   = (const float*)d_in[2];
    const float* ipw  = (const float*)d_in[3];
    const float* ipb  = (const float*)d_in[4];
    const float* opw  = (const float*)d_in[5];
    const float* opb  = (const float*)d_in[6];
    const float* pw   = (const float*)d_in[7];
    const float* pb   = (const float*)d_in[8];
    float* out = (float*)d_out;

    cudaFuncSetAttribute(k1_mma, cudaFuncAttributeMaxDynamicSharedMemorySize, K1_SMEM);

    pA<<<133, 256>>>(mt, ipw, ipb, pw, opw);
    pB<<<PB_P5B, 256>>>(ipw, ipb, pw, opb, mt);
    pC<<<1, 1024>>>(mask);

    k1_mma<<<736, 256, K1_SMEM>>>(cls);
    k2_attn<<<BB, 256>>>(cls, mask);
    dim3 g3(32, NSPLIT);
    k3_gemm<<<g3, 256>>>();
    k3b_final<<<(BB*NL + 255)/256, 256>>>(mask, pb, out);
}